// round 1
// baseline (speedup 1.0000x reference)
#include <cuda_runtime.h>

#define KDIM 32
#define TABN 1024
#define L2E  1.4426950408889634f
#define COEF 0.3989422804014327f

// Precomputed per-(a,b) constants: {A1, A0, B, C}
//   term = exp2(A + B*x + C*x^2)
//   A1 folds ln2(w21[a,b] * coef[a,b]) - mu^2/(2 sigma^2) * log2e
//   A0 folds ln2(w0[b] * w10[a,b] * coef[a,b]) - mu^2/(2 sigma^2) * log2e
__device__ float4 g_tab[TABN];

__device__ __forceinline__ float ex2(float x) {
    float r;
    asm("ex2.approx.ftz.f32 %0, %1;" : "=f"(r) : "f"(x));
    return r;
}

__global__ void precompute_kernel(const float* __restrict__ Wk0,
                                  const float* __restrict__ W10,
                                  const float* __restrict__ W21,
                                  const float* __restrict__ mu,
                                  const float* __restrict__ sigma) {
    __shared__ float mat10[TABN], mat21[TABN];
    __shared__ float s10[KDIM], s21[KDIM], w0s[KDIM];
    int tid = threadIdx.x;             // 1024 threads, tid = a*32 + b
    int b = tid & 31;

    float e10 = expf(W10[tid]);
    float e21 = expf(W21[tid]);
    mat10[tid] = e10;
    mat21[tid] = e21;
    __syncthreads();

    if (tid < KDIM) {
        float a10 = 0.f, a21 = 0.f;
        for (int i = 0; i < KDIM; i++) {
            a10 += mat10[i * KDIM + tid];   // column sums (softmax over axis 0)
            a21 += mat21[i * KDIM + tid];
        }
        s10[tid] = a10;
        s21[tid] = a21;
        float es = 0.f;
        for (int i = 0; i < KDIM; i++) es += expf(Wk0[i]);
        w0s[tid] = expf(Wk0[tid]) / es;
    }
    __syncthreads();

    float w10 = e10 / s10[b];
    float w21 = e21 / s21[b];
    float m = mu[tid];
    float s = sigma[tid];

    float inv_s  = 1.0f / s;
    float inv_s2 = inv_s * inv_s;
    float C  = -0.5f * inv_s2 * L2E;
    float B  = m * inv_s2 * L2E;
    float hm = 0.5f * m * m * inv_s2 * L2E;
    float A1 = log2f(w21 * COEF * inv_s) - hm;
    float A0 = log2f(w10 * w0s[b] * COEF * inv_s) - hm;

    g_tab[tid] = make_float4(A1, A0, B, C);
}

__global__ __launch_bounds__(128)
void tt_gauss_kernel(const float2* __restrict__ X, float* __restrict__ out, int N) {
    __shared__ float4 tab[TABN];
    for (int i = threadIdx.x; i < TABN; i += 128) tab[i] = g_tab[i];
    __syncthreads();

    int n = blockIdx.x * 128 + threadIdx.x;
    if (n >= N) return;

    float2 x = X[n];
    float x0 = x.x, x1 = x.y;

    // Phase 1: inner[b] = sum_a w21[a,b] * pdf(x1; mu[a,b], sigma[a,b])
    float inner[KDIM];
#pragma unroll
    for (int b = 0; b < KDIM; b++) inner[b] = 0.f;

#pragma unroll 1
    for (int a = 0; a < KDIM; a++) {
        const float4* row = &tab[a * KDIM];
#pragma unroll
        for (int b = 0; b < KDIM; b++) {
            float4 c = row[b];
            float q = fmaf(c.w, x1, c.z);   // C*x1 + B
            q = fmaf(q, x1, c.x);           // + A1
            inner[b] += ex2(q);
        }
    }

    // Phase 2: lik = sum_{a,b} w0[b]*w10[a,b]*pdf(x0; a,b) * inner[a]
    float lk[4] = {0.f, 0.f, 0.f, 0.f};
#pragma unroll 1
    for (int b = 0; b < KDIM; b++) {
        const float4* col = &tab[b];
#pragma unroll
        for (int a = 0; a < KDIM; a++) {
            float4 c = col[a * KDIM];
            float q = fmaf(c.w, x0, c.z);
            q = fmaf(q, x0, c.y);           // + A0 (includes w0[b]*w10[a,b])
            lk[a & 3] = fmaf(ex2(q), inner[a], lk[a & 3]);
        }
    }

    float lik = (lk[0] + lk[1]) + (lk[2] + lk[3]);
    out[n] = logf(lik + 2.220446049250313e-16f);
}

extern "C" void kernel_launch(void* const* d_in, const int* in_sizes, int n_in,
                              void* d_out, int out_size) {
    const float* X     = (const float*)d_in[0];
    const float* Wk0   = (const float*)d_in[1];
    const float* W10   = (const float*)d_in[2];
    const float* W21   = (const float*)d_in[3];
    const float* mu    = (const float*)d_in[4];
    const float* sigma = (const float*)d_in[5];
    int N = in_sizes[0] / 2;

    precompute_kernel<<<1, TABN>>>(Wk0, W10, W21, mu, sigma);
    tt_gauss_kernel<<<(N + 127) / 128, 128>>>((const float2*)X, (float*)d_out, N);
}

// round 2
// speedup vs baseline: 1.0023x; 1.0023x over previous
#include <cuda_runtime.h>

#define KDIM 32
#define TABN 1024
#define L2E  1.4426950408889634f
#define COEF 0.3989422804014327f

// Precomputed per-(a,b) constants: {A1, A0, B, C}
//   term = exp2(A + B*x + C*x^2)
//   A1 folds ln2(w21[a,b]*coef) - mu^2/(2 sigma^2)*log2e
//   A0 folds ln2(w0[b]*w10[a,b]*coef) - mu^2/(2 sigma^2)*log2e
__device__ float4 g_tab[TABN];

__device__ __forceinline__ float ex2(float x) {
    float r;
    asm("ex2.approx.ftz.f32 %0, %1;" : "=f"(r) : "f"(x));
    return r;
}

__global__ void precompute_kernel(const float* __restrict__ Wk0,
                                  const float* __restrict__ W10,
                                  const float* __restrict__ W21,
                                  const float* __restrict__ mu,
                                  const float* __restrict__ sigma) {
    __shared__ float mat10[TABN], mat21[TABN];
    __shared__ float s10[KDIM], s21[KDIM], w0s[KDIM];
    int tid = threadIdx.x;             // 1024 threads, tid = a*32 + b
    int b = tid & 31;

    float e10 = expf(W10[tid]);
    float e21 = expf(W21[tid]);
    mat10[tid] = e10;
    mat21[tid] = e21;
    __syncthreads();

    if (tid < KDIM) {
        float a10 = 0.f, a21 = 0.f;
        for (int i = 0; i < KDIM; i++) {
            a10 += mat10[i * KDIM + tid];   // column sums (softmax axis 0)
            a21 += mat21[i * KDIM + tid];
        }
        s10[tid] = a10;
        s21[tid] = a21;
        float es = 0.f;
        for (int i = 0; i < KDIM; i++) es += expf(Wk0[i]);
        w0s[tid] = expf(Wk0[tid]) / es;
    }
    __syncthreads();

    float w10 = e10 / s10[b];
    float w21 = e21 / s21[b];
    float m = mu[tid];
    float s = sigma[tid];

    float inv_s  = 1.0f / s;
    float inv_s2 = inv_s * inv_s;
    float C  = -0.5f * inv_s2 * L2E;
    float B  = m * inv_s2 * L2E;
    float hm = 0.5f * m * m * inv_s2 * L2E;
    float A1 = log2f(w21 * COEF * inv_s) - hm;
    float A0 = log2f(w10 * w0s[b] * COEF * inv_s) - hm;

    g_tab[tid] = make_float4(A1, A0, B, C);
}

// Two threads per sample: even/odd lanes split the 32x32 term grid in half,
// combine partials via lane^1 butterfly shuffles. Doubles resident warps
// (grid-limited occupancy 31% -> ~56%) at ~3% extra instructions.
__global__ __launch_bounds__(128)
void tt_gauss_kernel(const float2* __restrict__ X, float* __restrict__ out, int N) {
    __shared__ float4 tab[TABN];
    for (int i = threadIdx.x; i < TABN; i += 128) tab[i] = g_tab[i];
    __syncthreads();

    int gt = blockIdx.x * 128 + threadIdx.x;
    int n = gt >> 1;          // sample index (pair of threads per sample)
    int half = gt & 1;        // which half of the work
    if (n >= N) return;       // pairs exit together (same n), shuffles stay safe

    float2 x = X[n];
    float x0 = x.x, x1 = x.y;

    // Phase 1: inner[b] = sum_a w21[a,b] * pdf(x1; mu[a,b], sigma[a,b])
    // This thread covers a in [half*16, half*16+16).
    float inner[KDIM];
#pragma unroll
    for (int b = 0; b < KDIM; b++) inner[b] = 0.f;

    const float4* base1 = &tab[half * 16 * KDIM];
#pragma unroll 1
    for (int a = 0; a < 16; a++) {
        const float4* row = base1 + a * KDIM;
#pragma unroll
        for (int b = 0; b < KDIM; b++) {
            float4 c = row[b];
            float q = fmaf(c.w, x1, c.z);   // C*x1 + B
            q = fmaf(q, x1, c.x);           // + A1
            inner[b] += ex2(q);
        }
    }

    // Combine halves: partner thread (lane^1) holds the other 16 a-rows.
#pragma unroll
    for (int b = 0; b < KDIM; b++)
        inner[b] += __shfl_xor_sync(0xFFFFFFFFu, inner[b], 1);

    // Phase 2: lik = sum_{a,b} w0[b]*w10[a,b]*pdf(x0;a,b) * inner[a]
    // This thread covers b in [half*16, half*16+16).
    float lk[4] = {0.f, 0.f, 0.f, 0.f};
    const float4* base2 = &tab[half * 16];
#pragma unroll 1
    for (int bo = 0; bo < 16; bo++) {
        const float4* col = base2 + bo;
#pragma unroll
        for (int a = 0; a < KDIM; a++) {
            float4 c = col[a * KDIM];
            float q = fmaf(c.w, x0, c.z);
            q = fmaf(q, x0, c.y);           // + A0 (folds w0[b]*w10[a,b])
            lk[a & 3] = fmaf(ex2(q), inner[a], lk[a & 3]);
        }
    }

    float lik = (lk[0] + lk[1]) + (lk[2] + lk[3]);
    lik += __shfl_xor_sync(0xFFFFFFFFu, lik, 1);

    if (half == 0)
        out[n] = logf(lik + 2.220446049250313e-16f);
}

extern "C" void kernel_launch(void* const* d_in, const int* in_sizes, int n_in,
                              void* d_out, int out_size) {
    const float* X     = (const float*)d_in[0];
    const float* Wk0   = (const float*)d_in[1];
    const float* W10   = (const float*)d_in[2];
    const float* W21   = (const float*)d_in[3];
    const float* mu    = (const float*)d_in[4];
    const float* sigma = (const float*)d_in[5];
    int N = in_sizes[0] / 2;

    precompute_kernel<<<1, TABN>>>(Wk0, W10, W21, mu, sigma);

    int total_threads = 2 * N;
    int blocks = (total_threads + 127) / 128;
    tt_gauss_kernel<<<blocks, 128>>>((const float2*)X, (float*)d_out, N);
}

// round 3
// speedup vs baseline: 1.9034x; 1.8991x over previous
#include <cuda_runtime.h>

#define KDIM 32
#define TABN 1024
#define L2E  1.4426950408889634f
#define COEF 0.3989422804014327f
#define EPS  2.220446049250313e-16f

// Precomputed per-(a,b) constants: {A1, A0, B, C}
//   term = exp2(A + B*x + C*x^2)
//   A1 folds ln2(w21[a,b]*coef) - mu^2/(2 sigma^2)*log2e
//   A0 folds ln2(w0[b]*w10[a,b]*coef) - mu^2/(2 sigma^2)*log2e
__device__ float4 g_tab[TABN];

__device__ __forceinline__ float ex2(float x) {
    float r;
    asm("ex2.approx.ftz.f32 %0, %1;" : "=f"(r) : "f"(x));
    return r;
}

__global__ void precompute_kernel(const float* __restrict__ Wk0,
                                  const float* __restrict__ W10,
                                  const float* __restrict__ W21,
                                  const float* __restrict__ mu,
                                  const float* __restrict__ sigma) {
    __shared__ float mat10[TABN], mat21[TABN];
    __shared__ float s10[KDIM], s21[KDIM], w0s[KDIM];
    int tid = threadIdx.x;             // 1024 threads, tid = a*32 + b
    int b = tid & 31;

    float e10 = expf(W10[tid]);
    float e21 = expf(W21[tid]);
    mat10[tid] = e10;
    mat21[tid] = e21;
    __syncthreads();

    if (tid < KDIM) {
        float a10 = 0.f, a21 = 0.f;
        for (int i = 0; i < KDIM; i++) {
            a10 += mat10[i * KDIM + tid];   // column sums (softmax axis 0)
            a21 += mat21[i * KDIM + tid];
        }
        s10[tid] = a10;
        s21[tid] = a21;
        float es = 0.f;
        for (int i = 0; i < KDIM; i++) es += expf(Wk0[i]);
        w0s[tid] = expf(Wk0[tid]) / es;
    }
    __syncthreads();

    float w10 = e10 / s10[b];
    float w21 = e21 / s21[b];
    float m = mu[tid];
    float s = sigma[tid];

    float inv_s  = 1.0f / s;
    float inv_s2 = inv_s * inv_s;
    float C  = -0.5f * inv_s2 * L2E;
    float B  = m * inv_s2 * L2E;
    float hm = 0.5f * m * m * inv_s2 * L2E;
    float A1 = log2f(w21 * COEF * inv_s) - hm;
    float A0 = log2f(w10 * w0s[b] * COEF * inv_s) - hm;

    g_tab[tid] = make_float4(A1, A0, B, C);
}

// 2 samples per thread: one broadcast LDS.128 per term now feeds 64
// sample-terms per warp instead of 32, halving smem-crossbar cycles
// (173k -> 86k chip cycles) down to the MUFU ex2 floor.
__global__ __launch_bounds__(128)
void tt_gauss_kernel(const float2* __restrict__ X, float* __restrict__ out,
                     int N, int NH) {
    __shared__ float4 tab[TABN];
    for (int i = threadIdx.x; i < TABN; i += 128) tab[i] = g_tab[i];
    __syncthreads();

    int t = blockIdx.x * 128 + threadIdx.x;
    if (t >= NH) return;
    int n0 = t;
    int n1 = t + NH;
    bool has1 = (n1 < N);

    float2 pa = X[n0];
    float2 pb = has1 ? X[n1] : pa;
    float xa0 = pa.x, xa1 = pa.y;
    float xb0 = pb.x, xb1 = pb.y;

    // Phase 1: inner[b] = sum_a exp2(A1 + B*x1 + C*x1^2), per sample
    float innA[KDIM], innB[KDIM];
#pragma unroll
    for (int b = 0; b < KDIM; b++) { innA[b] = 0.f; innB[b] = 0.f; }

#pragma unroll 1
    for (int a = 0; a < KDIM; a++) {
        const float4* row = &tab[a * KDIM];
#pragma unroll
        for (int b = 0; b < KDIM; b++) {
            float4 c = row[b];
            float qa = fmaf(c.w, xa1, c.z);
            qa = fmaf(qa, xa1, c.x);
            innA[b] += ex2(qa);
            float qb = fmaf(c.w, xb1, c.z);
            qb = fmaf(qb, xb1, c.x);
            innB[b] += ex2(qb);
        }
    }

    // Phase 2: lik = sum_{a,b} exp2(A0 + B*x0 + C*x0^2) * inner[a]
    float lA0 = 0.f, lA1 = 0.f, lB0 = 0.f, lB1 = 0.f;
#pragma unroll 1
    for (int bo = 0; bo < KDIM; bo++) {
        const float4* col = &tab[bo];
#pragma unroll
        for (int a = 0; a < KDIM; a++) {
            float4 c = col[a * KDIM];
            float ua = fmaf(c.w, xa0, c.z);
            ua = fmaf(ua, xa0, c.y);
            float ub = fmaf(c.w, xb0, c.z);
            ub = fmaf(ub, xb0, c.y);
            if (a & 1) {
                lA1 = fmaf(ex2(ua), innA[a], lA1);
                lB1 = fmaf(ex2(ub), innB[a], lB1);
            } else {
                lA0 = fmaf(ex2(ua), innA[a], lA0);
                lB0 = fmaf(ex2(ub), innB[a], lB0);
            }
        }
    }

    out[n0] = logf((lA0 + lA1) + EPS);
    if (has1)
        out[n1] = logf((lB0 + lB1) + EPS);
}

extern "C" void kernel_launch(void* const* d_in, const int* in_sizes, int n_in,
                              void* d_out, int out_size) {
    const float* X     = (const float*)d_in[0];
    const float* Wk0   = (const float*)d_in[1];
    const float* W10   = (const float*)d_in[2];
    const float* W21   = (const float*)d_in[3];
    const float* mu    = (const float*)d_in[4];
    const float* sigma = (const float*)d_in[5];
    int N = in_sizes[0] / 2;
    int NH = (N + 1) / 2;

    precompute_kernel<<<1, TABN>>>(Wk0, W10, W21, mu, sigma);

    int blocks = (NH + 127) / 128;
    tt_gauss_kernel<<<blocks, 128>>>((const float2*)X, (float*)d_out, N, NH);
}

// round 4
// speedup vs baseline: 2.1628x; 1.1363x over previous
#include <cuda_runtime.h>

#define KDIM  32
#define TABN  1024
#define COEF  0.3989422804014327f
#define EPS   2.220446049250313e-16f

// Interpolation grid for the 64 univariate functions
#define G     160
#define GPAD  36                    // row stride in floats (bank rotation 4/row)
#define XMIN  (-6.5f)
#define XMAX  (6.5f)
#define DXI   ((G - 1) / (XMAX - XMIN))   // 159/13

// lik(x0,x1) = sum_a h_a(x0) * g_a(x1)   (rank-32 separable form)
// row-major: d_gt[t*GPAD + a] = g_a(x_t),  d_ht[t*GPAD + a] = h_a(x_t)
__device__ float d_gt[G * GPAD];
__device__ float d_ht[G * GPAD];
__device__ float d_w21n[TABN];      // w21 softmax-normalized (axis 0)
__device__ float d_wh[TABN];        // w10_norm[a,b] * w0[b]

// ---------------- Stage A: softmax weights (1 block) ----------------
__global__ void weights_kernel(const float* __restrict__ Wk0,
                               const float* __restrict__ W10,
                               const float* __restrict__ W21) {
    __shared__ float m10[TABN], m21[TABN];
    __shared__ float s10[KDIM], s21[KDIM], w0s[KDIM];
    int tid = threadIdx.x;          // tid = a*32 + b
    int b = tid & 31;

    float e10 = expf(W10[tid]);
    float e21 = expf(W21[tid]);
    m10[tid] = e10;
    m21[tid] = e21;
    __syncthreads();

    if (tid < KDIM) {
        float a10 = 0.f, a21 = 0.f;
        for (int i = 0; i < KDIM; i++) {
            a10 += m10[i * KDIM + tid];   // softmax over axis 0 (rows)
            a21 += m21[i * KDIM + tid];
        }
        s10[tid] = a10;
        s21[tid] = a21;
        float es = 0.f;
        for (int i = 0; i < KDIM; i++) es += expf(Wk0[i]);
        w0s[tid] = expf(Wk0[tid]) / es;
    }
    __syncthreads();

    d_w21n[tid] = e21 / s21[b];
    d_wh[tid]   = (e10 / s10[b]) * w0s[b];
}

// ---------------- Stage B: build the 64 function tables ----------------
// 2 tables * G rows * 32 funcs = 10240 outputs, one thread each, 32 exps per output.
__global__ void tables_kernel(const float* __restrict__ mu,
                              const float* __restrict__ sigma) {
    int idx = blockIdx.x * blockDim.x + threadIdx.x;
    if (idx >= 2 * G * KDIM) return;
    int tbl = idx / (G * KDIM);
    int rem = idx - tbl * (G * KDIM);
    int t = rem >> 5;
    int a = rem & 31;

    float x = XMIN + (float)t * ((XMAX - XMIN) / (G - 1));
    float acc = 0.f;
    if (tbl == 0) {
        // g_a(x) = sum_m w21n[m,a] * pdf(x; mu[m,a], sigma[m,a])
        for (int m = 0; m < KDIM; m++) {
            int e = m * KDIM + a;
            float s = sigma[e];
            float z = (x - mu[e]) / s;
            acc += d_w21n[e] * (COEF / s) * expf(-0.5f * z * z);
        }
        d_gt[t * GPAD + a] = acc;
    } else {
        // h_a(x) = sum_b w10n[a,b]*w0[b] * pdf(x; mu[a,b], sigma[a,b])
        for (int b = 0; b < KDIM; b++) {
            int e = a * KDIM + b;
            float s = sigma[e];
            float z = (x - mu[e]) / s;
            acc += d_wh[e] * (COEF / s) * expf(-0.5f * z * z);
        }
        d_ht[t * GPAD + a] = acc;
    }
}

// ---------------- Stage C: per-sample cubic interpolation ----------------
__global__ __launch_bounds__(256)
void interp_kernel(const float2* __restrict__ X, float* __restrict__ out, int N) {
    __shared__ float sg[G * GPAD];
    __shared__ float sh[G * GPAD];

    // Stage tables into smem (aligned float4 copies)
    {
        float4* dg = (float4*)sg;
        float4* dh = (float4*)sh;
        const float4* sgt = (const float4*)d_gt;
        const float4* sht = (const float4*)d_ht;
        const int n4 = G * GPAD / 4;   // 1440
        for (int i = threadIdx.x; i < n4; i += 256) {
            dg[i] = sgt[i];
            dh[i] = sht[i];
        }
    }
    __syncthreads();

    int n = blockIdx.x * 256 + threadIdx.x;
    if (n >= N) return;

    float2 p = X[n];

    // ---- lookup for x1 in g-table ----
    float u = (p.y - XMIN) * DXI;
    u = fminf(fmaxf(u, 1.0f), (float)(G - 2) - 1e-3f);
    int j = (int)u;
    float t = u - (float)j;
    float tm1 = t - 1.f, tm2 = t - 2.f, tp1 = t + 1.f;
    float ga = -t * tm1 * tm2 * (1.f / 6.f);
    float gb = tp1 * tm1 * tm2 * 0.5f;
    float gc = -tp1 * t * tm2 * 0.5f;
    float gd = tp1 * t * tm1 * (1.f / 6.f);

    const float* r0 = sg + (j - 1) * GPAD;
    const float* r1 = r0 + GPAD;
    const float* r2 = r1 + GPAD;
    const float* r3 = r2 + GPAD;

    float gval[KDIM];
#pragma unroll
    for (int c = 0; c < 8; c++) {
        float4 a0 = *(const float4*)(r0 + 4 * c);
        float4 a1 = *(const float4*)(r1 + 4 * c);
        float4 a2 = *(const float4*)(r2 + 4 * c);
        float4 a3 = *(const float4*)(r3 + 4 * c);
        gval[4*c+0] = fmaf(ga, a0.x, fmaf(gb, a1.x, fmaf(gc, a2.x, gd * a3.x)));
        gval[4*c+1] = fmaf(ga, a0.y, fmaf(gb, a1.y, fmaf(gc, a2.y, gd * a3.y)));
        gval[4*c+2] = fmaf(ga, a0.z, fmaf(gb, a1.z, fmaf(gc, a2.z, gd * a3.z)));
        gval[4*c+3] = fmaf(ga, a0.w, fmaf(gb, a1.w, fmaf(gc, a2.w, gd * a3.w)));
    }

    // ---- lookup for x0 in h-table, fused with dot product ----
    u = (p.x - XMIN) * DXI;
    u = fminf(fmaxf(u, 1.0f), (float)(G - 2) - 1e-3f);
    j = (int)u;
    t = u - (float)j;
    tm1 = t - 1.f; tm2 = t - 2.f; tp1 = t + 1.f;
    float ha = -t * tm1 * tm2 * (1.f / 6.f);
    float hb = tp1 * tm1 * tm2 * 0.5f;
    float hc = -tp1 * t * tm2 * 0.5f;
    float hd = tp1 * t * tm1 * (1.f / 6.f);

    const float* q0 = sh + (j - 1) * GPAD;
    const float* q1 = q0 + GPAD;
    const float* q2 = q1 + GPAD;
    const float* q3 = q2 + GPAD;

    float lik0 = 0.f, lik1 = 0.f;
#pragma unroll
    for (int c = 0; c < 8; c++) {
        float4 b0 = *(const float4*)(q0 + 4 * c);
        float4 b1 = *(const float4*)(q1 + 4 * c);
        float4 b2 = *(const float4*)(q2 + 4 * c);
        float4 b3 = *(const float4*)(q3 + 4 * c);
        float h0 = fmaf(ha, b0.x, fmaf(hb, b1.x, fmaf(hc, b2.x, hd * b3.x)));
        float h1 = fmaf(ha, b0.y, fmaf(hb, b1.y, fmaf(hc, b2.y, hd * b3.y)));
        float h2 = fmaf(ha, b0.z, fmaf(hb, b1.z, fmaf(hc, b2.z, hd * b3.z)));
        float h3 = fmaf(ha, b0.w, fmaf(hb, b1.w, fmaf(hc, b2.w, hd * b3.w)));
        lik0 = fmaf(h0, gval[4*c+0], lik0);
        lik1 = fmaf(h1, gval[4*c+1], lik1);
        lik0 = fmaf(h2, gval[4*c+2], lik0);
        lik1 = fmaf(h3, gval[4*c+3], lik1);
    }

    float lik = fmaxf(lik0 + lik1, 0.f);   // guard vs. interp undershoot in tails
    out[n] = logf(lik + EPS);
}

extern "C" void kernel_launch(void* const* d_in, const int* in_sizes, int n_in,
                              void* d_out, int out_size) {
    const float* X     = (const float*)d_in[0];
    const float* Wk0   = (const float*)d_in[1];
    const float* W10   = (const float*)d_in[2];
    const float* W21   = (const float*)d_in[3];
    const float* mu    = (const float*)d_in[4];
    const float* sigma = (const float*)d_in[5];
    int N = in_sizes[0] / 2;

    weights_kernel<<<1, TABN>>>(Wk0, W10, W21);

    int nb_tab = (2 * G * KDIM + 255) / 256;
    tables_kernel<<<nb_tab, 256>>>(mu, sigma);

    int nb = (N + 255) / 256;
    interp_kernel<<<nb, 256>>>((const float2*)X, (float*)d_out, N);
}

// round 5
// speedup vs baseline: 5.2280x; 2.4172x over previous
#include <cuda_runtime.h>

#define KDIM  32
#define TABN  1024
#define COEF  0.3989422804014327f
#define EPS   2.220446049250313e-16f

// Interpolation grid for the 64 univariate functions
#define G     160
#define GPAD  36                    // row stride in floats (bank rotation 4/row)
#define XMIN  (-6.5f)
#define XMAX  (6.5f)
#define DX    ((XMAX - XMIN) / (G - 1))
#define DXI   ((G - 1) / (XMAX - XMIN))

// lik(x0,x1) = sum_a h_a(x0) * g_a(x1)   (rank-32 separable form)
__device__ float d_gt[G * GPAD];    // d_gt[t*GPAD + a] = g_a(x_t)
__device__ float d_ht[G * GPAD];    // d_ht[t*GPAD + a] = h_a(x_t)

__device__ __forceinline__ float ex2(float x) {
    float r;
    asm("ex2.approx.ftz.f32 %0, %1;" : "=f"(r) : "f"(x));
    return r;
}

// ---------------- Fused precompute: weights + tables in one kernel ----------
// 20 blocks x 512 threads = 10240 table outputs, one per thread. Each block
// redundantly recomputes the (tiny) softmax weights in smem, builds per-entry
// constants, then evaluates its outputs from smem with fast ex2 — no fdiv or
// L2 loads in the inner loop.
#define TB_BLOCKS  20
#define TB_THREADS 512

__global__ __launch_bounds__(TB_THREADS)
void tables_fused_kernel(const float* __restrict__ Wk0,
                         const float* __restrict__ W10,
                         const float* __restrict__ W21,
                         const float* __restrict__ mu,
                         const float* __restrict__ sigma) {
    __shared__ float sw10[TABN], sw21[TABN];
    __shared__ float s10[KDIM], s21[KDIM], w0n[KDIM];
    __shared__ float wcg[TABN], wch[TABN], smu[TABN], sinv[TABN];
    int tid = threadIdx.x;

    for (int i = tid; i < TABN; i += TB_THREADS) {
        sw10[i] = expf(W10[i]);
        sw21[i] = expf(W21[i]);
    }
    __syncthreads();

    if (tid < KDIM) {
        float a10 = 0.f, a21 = 0.f;
        for (int i = 0; i < KDIM; i++) {
            a10 += sw10[i * KDIM + tid];   // softmax over axis 0
            a21 += sw21[i * KDIM + tid];
        }
        s10[tid] = a10;
        s21[tid] = a21;
        float es = 0.f;
        for (int i = 0; i < KDIM; i++) es += expf(Wk0[i]);
        w0n[tid] = expf(Wk0[tid]) / es;
    }
    __syncthreads();

    for (int i = tid; i < TABN; i += TB_THREADS) {
        int b = i & 31;
        float s = sigma[i];
        float inv = 1.0f / s;
        smu[i]  = mu[i];
        sinv[i] = inv;
        wcg[i] = (sw21[i] / s21[b]) * COEF * inv;               // w21n * coef
        wch[i] = (sw10[i] / s10[b]) * w0n[b] * COEF * inv;      // w10n*w0 * coef
    }
    __syncthreads();

    int idx = blockIdx.x * TB_THREADS + tid;      // [0, 2*G*KDIM)
    int tbl = idx / (G * KDIM);
    int rem = idx - tbl * (G * KDIM);
    int t = rem >> 5;
    int a = rem & 31;

    float x = XMIN + (float)t * DX;
    const float K2 = -0.72134752044448170f;       // -0.5 * log2(e)
    float acc = 0.f;
    if (tbl == 0) {
        // g_a(x) = sum_m w21n[m,a] * pdf(x; mu[m,a], sigma[m,a])
#pragma unroll
        for (int m = 0; m < KDIM; m++) {
            int e = m * KDIM + a;                 // lanes stride-1: conflict-free
            float z = (x - smu[e]) * sinv[e];
            acc += wcg[e] * ex2(K2 * z * z);
        }
        d_gt[t * GPAD + a] = acc;
    } else {
        // h_a(x) = sum_b w10n[a,b]*w0[b] * pdf(x; mu[a,b], sigma[a,b])
#pragma unroll
        for (int m = 0; m < KDIM; m++) {
            int b = (m + a) & 31;                 // skew: avoid 32-way conflicts
            int e = a * KDIM + b;
            float z = (x - smu[e]) * sinv[e];
            acc += wch[e] * ex2(K2 * z * z);
        }
        d_ht[t * GPAD + a] = acc;
    }
}

// ---------------- Per-sample cubic interpolation ----------------
__global__ __launch_bounds__(256)
void interp_kernel(const float2* __restrict__ X, float* __restrict__ out, int N) {
    __shared__ float sg[G * GPAD];
    __shared__ float sh[G * GPAD];

    {
        float4* dg = (float4*)sg;
        float4* dh = (float4*)sh;
        const float4* sgt = (const float4*)d_gt;
        const float4* sht = (const float4*)d_ht;
        const int n4 = G * GPAD / 4;   // 1440
        for (int i = threadIdx.x; i < n4; i += 256) {
            dg[i] = sgt[i];
            dh[i] = sht[i];
        }
    }
    __syncthreads();

    int n = blockIdx.x * 256 + threadIdx.x;
    if (n >= N) return;

    float2 p = X[n];

    // ---- x1 lookup in g-table ----
    float u = (p.y - XMIN) * DXI;
    u = fminf(fmaxf(u, 1.0f), (float)(G - 2) - 1e-3f);
    int j = (int)u;
    float t = u - (float)j;
    float tm1 = t - 1.f, tm2 = t - 2.f, tp1 = t + 1.f;
    float ga = -t * tm1 * tm2 * (1.f / 6.f);
    float gb = tp1 * tm1 * tm2 * 0.5f;
    float gc = -tp1 * t * tm2 * 0.5f;
    float gd = tp1 * t * tm1 * (1.f / 6.f);

    const float* r0 = sg + (j - 1) * GPAD;
    const float* r1 = r0 + GPAD;
    const float* r2 = r1 + GPAD;
    const float* r3 = r2 + GPAD;

    float gval[KDIM];
#pragma unroll
    for (int c = 0; c < 8; c++) {
        float4 a0 = *(const float4*)(r0 + 4 * c);
        float4 a1 = *(const float4*)(r1 + 4 * c);
        float4 a2 = *(const float4*)(r2 + 4 * c);
        float4 a3 = *(const float4*)(r3 + 4 * c);
        gval[4*c+0] = fmaf(ga, a0.x, fmaf(gb, a1.x, fmaf(gc, a2.x, gd * a3.x)));
        gval[4*c+1] = fmaf(ga, a0.y, fmaf(gb, a1.y, fmaf(gc, a2.y, gd * a3.y)));
        gval[4*c+2] = fmaf(ga, a0.z, fmaf(gb, a1.z, fmaf(gc, a2.z, gd * a3.z)));
        gval[4*c+3] = fmaf(ga, a0.w, fmaf(gb, a1.w, fmaf(gc, a2.w, gd * a3.w)));
    }

    // ---- x0 lookup in h-table, fused with dot product ----
    u = (p.x - XMIN) * DXI;
    u = fminf(fmaxf(u, 1.0f), (float)(G - 2) - 1e-3f);
    j = (int)u;
    t = u - (float)j;
    tm1 = t - 1.f; tm2 = t - 2.f; tp1 = t + 1.f;
    float ha = -t * tm1 * tm2 * (1.f / 6.f);
    float hb = tp1 * tm1 * tm2 * 0.5f;
    float hc = -tp1 * t * tm2 * 0.5f;
    float hd = tp1 * t * tm1 * (1.f / 6.f);

    const float* q0 = sh + (j - 1) * GPAD;
    const float* q1 = q0 + GPAD;
    const float* q2 = q1 + GPAD;
    const float* q3 = q2 + GPAD;

    float lik0 = 0.f, lik1 = 0.f;
#pragma unroll
    for (int c = 0; c < 8; c++) {
        float4 b0 = *(const float4*)(q0 + 4 * c);
        float4 b1 = *(const float4*)(q1 + 4 * c);
        float4 b2 = *(const float4*)(q2 + 4 * c);
        float4 b3 = *(const float4*)(q3 + 4 * c);
        float h0 = fmaf(ha, b0.x, fmaf(hb, b1.x, fmaf(hc, b2.x, hd * b3.x)));
        float h1 = fmaf(ha, b0.y, fmaf(hb, b1.y, fmaf(hc, b2.y, hd * b3.y)));
        float h2 = fmaf(ha, b0.z, fmaf(hb, b1.z, fmaf(hc, b2.z, hd * b3.z)));
        float h3 = fmaf(ha, b0.w, fmaf(hb, b1.w, fmaf(hc, b2.w, hd * b3.w)));
        lik0 = fmaf(h0, gval[4*c+0], lik0);
        lik1 = fmaf(h1, gval[4*c+1], lik1);
        lik0 = fmaf(h2, gval[4*c+2], lik0);
        lik1 = fmaf(h3, gval[4*c+3], lik1);
    }

    float lik = fmaxf(lik0 + lik1, 0.f);   // guard vs. interp undershoot
    out[n] = logf(lik + EPS);
}

extern "C" void kernel_launch(void* const* d_in, const int* in_sizes, int n_in,
                              void* d_out, int out_size) {
    const float* X     = (const float*)d_in[0];
    const float* Wk0   = (const float*)d_in[1];
    const float* W10   = (const float*)d_in[2];
    const float* W21   = (const float*)d_in[3];
    const float* mu    = (const float*)d_in[4];
    const float* sigma = (const float*)d_in[5];
    int N = in_sizes[0] / 2;

    tables_fused_kernel<<<TB_BLOCKS, TB_THREADS>>>(Wk0, W10, W21, mu, sigma);

    int nb = (N + 255) / 256;
    interp_kernel<<<nb, 256>>>((const float2*)X, (float*)d_out, N);
}